// round 15
// baseline (speedup 1.0000x reference)
#include <cuda_runtime.h>

#define DIM  160
#define RP   164   // padded smem row (floats)
#define NB   2

// scale0: k=10 s=2 O=71 | scale1: k=20 s=5 O=25 | scale2: k=40 s=10 O=9
#define O0 71
#define O1 25
#define O2 9
#define NZ0 80
#define NZ1c 160
#define NZ2 80

#define FS0 (NB*NZ0*O0*O0)
#define FS1 (NB*NZ1c*O1*O1)
#define FS2 (NB*NZ2*O2*O2)
#define OFF0 0
#define OFF1 (5*FS0)
#define OFF2 (OFF1 + 5*FS1)

#define N3_0 (NB*O0*O0*O0)
#define N3_1 (NB*O1*O1*O1)
#define N3_2 (NB*O2*O2*O2)

// pass34: sc0 strips of 3 outputs, 24 strips (R9 config)
#define NSTRIP0 24
#define STRIP0  3
#define NT0S   (NB*NSTRIP0*O0*O0)          // 241,968
#define NBLK0S ((NT0S + 255) / 256)        // 946
#define NBLK1  ((N3_1 + 255) / 256)        // 123
#define NBLK2  ((N3_2 + 255) / 256)        //   6
#define TOTBLK (NBLK0S + NBLK1 + NBLK2)    // 1075

#define PB0 0
#define PB1 960
#define PB2 1088

__device__ float g_bufB[OFF2 + 5*FS2];   // ~20.4 MB
__device__ float g_partials[1280];
__device__ unsigned int g_count = 0;

#define RAWF (2*16*RP)    // 16 rows x 2 vols = 5248 floats
#define CH0 36

// per-kernel smem sizes
#define SMEM_SC1  ((NZ1c*5*O1 + RAWF) * (int)sizeof(float))                 // 100,992 B
#define SMEM_SC02 ((NZ0*5*CH0 + NZ0*5*O2 + RAWF) * (int)sizeof(float))     //  92,992 B

// ---------------------------------------------------------------------------
__device__ __forceinline__ void ldrow(const float* __restrict__ p, int lane,
                                      float4& r0, float4& r1) {
    const float4* q = (const float4*)p;
    r0 = q[lane];
    if (lane < 8) r1 = q[32 + lane];
}
__device__ __forceinline__ void strow(float* d, int lane,
                                      const float4& r0, const float4& r1) {
    float4* q = (float4*)d;
    q[lane] = r0;
    if (lane < 8) q[32 + lane] = r1;
}

template<int K>
__device__ __forceinline__ void win5(const float* xr, const float* yr, int z2s,
                                     float* out, int stride) {
    float a0 = 0.f, a1 = 0.f, a2 = 0.f, a3 = 0.f, a4 = 0.f;
#pragma unroll
    for (int t = 0; t < K; t++) {
        float xv = xr[z2s + 2 * t];
        float yv = yr[z2s + 2 * t];
        a0 += xv; a1 += yv; a2 += xv * xv; a3 += yv * yv; a4 += xv * yv;
    }
    out[0 * stride] = a0;
    out[1 * stride] = a1;
    out[2 * stride] = a2;
    out[3 * stride] = a3;
    out[4 * stride] = a4;
}

// ---------------------------------------------------------------------------
// fused_sc1 (R9 body): one block per (b,z0), 512 threads, 10 batches of 16
// rows, register double-buffer. zwin[160][5][25]; phase2 taps = 5*o1 + 2t.
// ---------------------------------------------------------------------------
__global__ __launch_bounds__(512) void fused_sc1(const float* __restrict__ x,
                                                 const float* __restrict__ y) {
    extern __shared__ float sm[];
    const int O = O1, NZ = NZ1c;
    float* zwin = sm;                    // [NZ][5][O] = 20000
    float* raw  = sm + NZ * 5 * O;       // 80000 B offset -> 16B aligned

    int z0 = blockIdx.x % DIM;
    int b  = blockIdx.x / DIM;
    int w    = threadIdx.x >> 5;
    int lane = threadIdx.x & 31;
    const float* xbase = x + (size_t)(b * DIM + z0) * DIM * DIM;
    const float* ybase = y + (size_t)(b * DIM + z0) * DIM * DIM;

    float4 fx0, fx1, fy0, fy1;
    ldrow(xbase + (size_t)w * DIM, lane, fx0, fx1);
    ldrow(ybase + (size_t)w * DIM, lane, fy0, fy1);

    for (int ib = 0; ib < 10; ib++) {
        __syncthreads();
        strow(raw + w * RP,        lane, fx0, fx1);
        strow(raw + (16 + w) * RP, lane, fy0, fy1);
        if (ib < 9) {
            int z1 = (ib + 1) * 16 + w;
            ldrow(xbase + (size_t)z1 * DIM, lane, fx0, fx1);
            ldrow(ybase + (size_t)z1 * DIM, lane, fy0, fy1);
        }
        __syncthreads();
        if (threadIdx.x < 16 * O) {
            int rl = threadIdx.x / O;
            int o2 = threadIdx.x % O;
            win5<20>(raw + rl * RP, raw + (16 + rl) * RP, 5 * o2,
                     zwin + (size_t)(ib * 16 + rl) * 125 + o2, O);
        }
    }
    __syncthreads();

    const int ITEMS = 5 * O * O;
    for (int item = threadIdx.x; item < ITEMS; item += 512) {
        int f   = item / (O * O);
        int rem = item % (O * O);
        int o1  = rem / O;
        int o2  = rem % O;
        float acc = 0.f;
#pragma unroll
        for (int t = 0; t < 20; t++)
            acc += zwin[(size_t)(5 * o1 + 2 * t) * 125 + f * O + o2];
        g_bufB[OFF1 + f * FS1 + (((b * NZ) + z0) * O + o1) * O + o2] = acc;
    }
}

// ---------------------------------------------------------------------------
// fused_sc02 (R9 body): even planes (z = 2*zi), CH0=36, 2 chunks;
// zwin2 in chunk 0. 512 threads, 5 batches of 16 even rows.
// ---------------------------------------------------------------------------
__global__ __launch_bounds__(512) void fused_sc02(const float* __restrict__ x,
                                                  const float* __restrict__ y) {
    extern __shared__ float sm[];
    const int NZ = 80;
    float* zwin0 = sm;                          // [80][5][CH0] = 14400
    float* zwin2 = sm + NZ * 5 * CH0;           // [80][5][9]   = 3600
    float* raw   = zwin2 + NZ * 5 * O2;         // 18000 floats (72000B, aligned)

    int bid = blockIdx.x;
    int ch  = bid & 1;  bid >>= 1;
    int z0i = bid % NZ;
    int b   = bid / NZ;
    int z0  = 2 * z0i;
    int obase = ch * CH0;
    int w    = threadIdx.x >> 5;
    int lane = threadIdx.x & 31;
    const float* xbase = x + (size_t)(b * DIM + z0) * DIM * DIM;
    const float* ybase = y + (size_t)(b * DIM + z0) * DIM * DIM;

    float4 fx0, fx1, fy0, fy1;
    ldrow(xbase + (size_t)(2 * w) * DIM, lane, fx0, fx1);
    ldrow(ybase + (size_t)(2 * w) * DIM, lane, fy0, fy1);

    for (int ib = 0; ib < 5; ib++) {
        int rb = ib * 16;
        __syncthreads();
        strow(raw + w * RP,        lane, fx0, fx1);
        strow(raw + (16 + w) * RP, lane, fy0, fy1);
        if (ib < 4) {
            int z1 = 2 * (rb + 16 + w);
            ldrow(xbase + (size_t)z1 * DIM, lane, fx0, fx1);
            ldrow(ybase + (size_t)z1 * DIM, lane, fy0, fy1);
        }
        __syncthreads();

        int nit = (ch == 0) ? (16 * CH0 + 16 * O2) : (16 * CH0);
        for (int it = threadIdx.x; it < nit; it += 512) {
            if (it < 16 * CH0) {
                int rl  = it / CH0;
                int o2l = it % CH0;
                int o2  = obase + o2l;
                if (o2 < O0)
                    win5<10>(raw + rl * RP, raw + (16 + rl) * RP, 2 * o2,
                             zwin0 + (size_t)(rb + rl) * 5 * CH0 + o2l, CH0);
            } else {
                int it2 = it - 16 * CH0;
                int rl = it2 / O2;
                int o2 = it2 % O2;
                win5<40>(raw + rl * RP, raw + (16 + rl) * RP, 10 * o2,
                         zwin2 + (size_t)(rb + rl) * 5 * O2 + o2, O2);
            }
        }
    }
    __syncthreads();

    // phase2 sc0: taps = 10 consecutive compact planes
    {
        const int ITEMS = 5 * O0 * CH0;
        for (int item = threadIdx.x; item < ITEMS; item += 512) {
            int f   = item / (O0 * CH0);
            int rem = item % (O0 * CH0);
            int o1  = rem / CH0;
            int o2l = rem % CH0;
            int o2  = obase + o2l;
            if (o2 >= O0) continue;
            float acc = 0.f;
#pragma unroll
            for (int t = 0; t < 10; t++)
                acc += zwin0[(size_t)(o1 + t) * 5 * CH0 + f * CH0 + o2l];
            g_bufB[OFF0 + f * FS0 + (((b * NZ) + z0i) * O0 + o1) * O0 + o2] = acc;
        }
    }
    // phase2 sc2: taps = compact planes 5*o1 + t, t<40 (chunk 0 only)
    if (ch == 0) {
        const int ITEMS = 5 * O2 * O2;
        for (int item = threadIdx.x; item < ITEMS; item += 512) {
            int f   = item / (O2 * O2);
            int rem = item % (O2 * O2);
            int o1  = rem / O2;
            int o2  = rem % O2;
            float acc = 0.f;
#pragma unroll
            for (int t = 0; t < 40; t++)
                acc += zwin2[(size_t)(5 * o1 + t) * 5 * O2 + f * O2 + o2];
            g_bufB[OFF2 + f * FS2 + (((b * NZ) + z0i) * O2 + o1) * O2 + o2] = acc;
        }
    }
}

// ---------------------------------------------------------------------------
// pass34 (R9) + fused finalize
// ---------------------------------------------------------------------------
__device__ __forceinline__ float lncc_eval(float s0, float s1, float s2,
                                           float s3, float s4, float numel) {
    float xm = s0 / numel;
    float ym = s1 / numel;
    float cross = s4 - ym * s0 - xm * s1 + ym * xm * numel;
    float xvar  = s2 - 2.f * xm * s0 + xm * xm * numel;
    float yvar  = s3 - 2.f * ym * s1 + ym * ym * numel;
    return cross * cross / (xvar * yvar + 1e-5f);
}

template<int K, int O, int NZ, int B0, int TS, int OFF, int FS, int N3>
__device__ __forceinline__ float pass34_gather(int blk) {
    const float numel = (float)K * (float)K * (float)K;
    int idx = blk * 256 + threadIdx.x;
    if (idx >= N3) return 0.f;
    int o2 = idx % O;
    int r  = idx / O;
    int o1 = r % O;  r /= O;
    int o0 = r % O;
    int b  = r / O;
    int inbase = ((b * NZ + B0 * o0) * O + o1) * O + o2;
    const int tapstride = TS * O * O;
    float acc[5];
#pragma unroll
    for (int f = 0; f < 5; f++) {
        const float* p = g_bufB + OFF + f * FS + inbase;
        float a = 0.f;
#pragma unroll
        for (int t = 0; t < K; t++) a += p[t * tapstride];
        acc[f] = a;
    }
    return lncc_eval(acc[0], acc[1], acc[2], acc[3], acc[4], numel);
}

__device__ __forceinline__ float pass34_strip0(int blk) {
    int idx = blk * 256 + threadIdx.x;
    if (idx >= NT0S) return 0.f;
    int o2 = idx % O0;
    int r  = idx / O0;
    int o1 = r % O0;  r /= O0;
    int strip = r % NSTRIP0;
    int b     = r / NSTRIP0;
    int o0s = strip * STRIP0;
    int o0e = (o0s + STRIP0 < O0) ? o0s + STRIP0 : O0;
    const int PS = O0 * O0;
    int base = ((b * NZ0) * O0 + o1) * O0 + o2;
    const float* p0 = g_bufB + OFF0 + base;
    float a0 = 0.f, a1 = 0.f, a2 = 0.f, a3 = 0.f, a4 = 0.f;
    float vsum = 0.f;
    for (int z = o0s; z < o0e + 9; z++) {
        int off = z * PS;
        a0 += p0[off];
        a1 += p0[off + 1 * FS0];
        a2 += p0[off + 2 * FS0];
        a3 += p0[off + 3 * FS0];
        a4 += p0[off + 4 * FS0];
        if (z >= o0s + 9) {
            vsum += lncc_eval(a0, a1, a2, a3, a4, 1000.0f);
            int offt = (z - 9) * PS;
            a0 -= p0[offt];
            a1 -= p0[offt + 1 * FS0];
            a2 -= p0[offt + 2 * FS0];
            a3 -= p0[offt + 3 * FS0];
            a4 -= p0[offt + 4 * FS0];
        }
    }
    return vsum;
}

__global__ __launch_bounds__(256) void pass34_all(float* __restrict__ out) {
    int bb = blockIdx.x;
    float v;
    int pslot;
    if (bb < NBLK0S) {
        v = pass34_strip0(bb);
        pslot = PB0 + bb;
    } else if (bb < NBLK0S + NBLK1) {
        v = pass34_gather<20, O1, NZ1c, 5, 2, OFF1, FS1, N3_1>(bb - NBLK0S);
        pslot = PB1 + (bb - NBLK0S);
    } else {
        v = pass34_gather<40, O2, NZ2, 5, 1, OFF2, FS2, N3_2>(bb - NBLK0S - NBLK1);
        pslot = PB2 + (bb - NBLK0S - NBLK1);
    }

    __shared__ float wsum[8];
    int lane = threadIdx.x & 31;
    int wid  = threadIdx.x >> 5;
#pragma unroll
    for (int o = 16; o > 0; o >>= 1) v += __shfl_down_sync(0xffffffffu, v, o);
    if (lane == 0) wsum[wid] = v;
    __syncthreads();
    if (wid == 0) {
        v = (lane < 8) ? wsum[lane] : 0.f;
#pragma unroll
        for (int o = 4; o > 0; o >>= 1) v += __shfl_down_sync(0xffffffffu, v, o);
        if (lane == 0) g_partials[pslot] = v;
    }

    __shared__ bool isLast;
    __threadfence();
    if (threadIdx.x == 0) {
        unsigned int old = atomicAdd(&g_count, 1u);
        isLast = (old == TOTBLK - 1);
    }
    __syncthreads();
    if (!isLast) return;
    __threadfence();

    __shared__ float sh[256];
    const int   pbase[3] = {PB0, PB1, PB2};
    const int   nblk[3]  = {NBLK0S, NBLK1, NBLK2};
    const float ninv[3]  = {1.0f / N3_0, 1.0f / N3_1, 1.0f / N3_2};
    const float wsc[3]   = {0.1f, 0.3f, 0.6f};
    float total = 0.f;
    for (int sc = 0; sc < 3; sc++) {
        float a = 0.f;
        for (int i = threadIdx.x; i < nblk[sc]; i += 256) a += g_partials[pbase[sc] + i];
        sh[threadIdx.x] = a;
        __syncthreads();
#pragma unroll
        for (int st = 128; st > 0; st >>= 1) {
            if (threadIdx.x < st) sh[threadIdx.x] += sh[threadIdx.x + st];
            __syncthreads();
        }
        if (threadIdx.x == 0) total += (1.0f - sh[0] * ninv[sc]) * wsc[sc];
        __syncthreads();
    }
    if (threadIdx.x == 0) {
        out[0] = total;
        g_count = 0;
    }
}

extern "C" void kernel_launch(void* const* d_in, const int* in_sizes, int n_in,
                              void* d_out, int out_size) {
    const float* x = (const float*)d_in[0];
    const float* y = (const float*)d_in[1];
    float* out = (float*)d_out;

    cudaFuncSetAttribute(fused_sc1,
                         cudaFuncAttributeMaxDynamicSharedMemorySize, SMEM_SC1);
    cudaFuncSetAttribute(fused_sc02,
                         cudaFuncAttributeMaxDynamicSharedMemorySize, SMEM_SC02);

    fused_sc1 <<<NB * DIM,     512, SMEM_SC1 >>>(x, y);
    fused_sc02<<<NB * NZ0 * 2, 512, SMEM_SC02>>>(x, y);
    pass34_all<<<TOTBLK, 256>>>(out);
}

// round 16
// speedup vs baseline: 1.1169x; 1.1169x over previous
#include <cuda_runtime.h>

#define DIM  160
#define RP   164   // padded smem row (floats)
#define NB   2

// scale0: k=10 s=2 O=71 | scale1: k=20 s=5 O=25 | scale2: k=40 s=10 O=9
#define O0 71
#define O1 25
#define O2 9
#define NZ0 80
#define NZ1c 160
#define NZ2 80

#define FS0 (NB*NZ0*O0*O0)
#define FS1 (NB*NZ1c*O1*O1)
#define FS2 (NB*NZ2*O2*O2)
#define OFF0 0
#define OFF1 (5*FS0)
#define OFF2 (OFF1 + 5*FS1)

#define N3_0 (NB*O0*O0*O0)
#define N3_1 (NB*O1*O1*O1)
#define N3_2 (NB*O2*O2*O2)

// pass34: sc0 strips of 3 outputs, 24 strips (champion config)
#define NSTRIP0 24
#define STRIP0  3
#define NT0S   (NB*NSTRIP0*O0*O0)          // 241,968
#define NBLK0S ((NT0S + 255) / 256)        // 946
#define NBLK1  ((N3_1 + 255) / 256)        // 123
#define NBLK2  ((N3_2 + 255) / 256)        //   6
#define TOTBLK (NBLK0S + NBLK1 + NBLK2)    // 1075

#define PB0 0
#define PB1 960
#define PB2 1088

__device__ float g_bufB[OFF2 + 5*FS2];   // ~20.4 MB
__device__ float g_partials[1280];
__device__ unsigned int g_count = 0;

#define RAWF (2*16*RP)    // 16 rows x 2 vols = 5248 floats
#define CH0 36

// fused grid: sc1 (full z) then sc02 (CH0=36, 2 chunks) — merged (champion)
#define G1  (NB*DIM)       // 320
#define G02 (NB*NZ0*2)     // 320
#define GALL (G1 + G02)

// sc1 smem: zwin 20000 + raw 5248 + gs 16*160=2560 = 27808 floats = 111,232 B
// sc02 smem: 14400 + 3600 + 5248 = 23248 floats (fits under the same max)
#define GS1OFF (NZ1c*5*O1 + RAWF)     // 25248
#define SMEM_ALL ((GS1OFF + 16*160) * (int)sizeof(float))

// ---------------------------------------------------------------------------
__device__ __forceinline__ void ldrow(const float* __restrict__ p, int lane,
                                      float4& r0, float4& r1) {
    const float4* q = (const float4*)p;
    r0 = q[lane];
    if (lane < 8) r1 = q[32 + lane];
}
__device__ __forceinline__ void strow(float* d, int lane,
                                      const float4& r0, const float4& r1) {
    float4* q = (float4*)d;
    q[lane] = r0;
    if (lane < 8) q[32 + lane] = r1;
}

template<int K>
__device__ __forceinline__ void win5(const float* xr, const float* yr, int z2s,
                                     float* out, int stride) {
    float a0 = 0.f, a1 = 0.f, a2 = 0.f, a3 = 0.f, a4 = 0.f;
#pragma unroll
    for (int t = 0; t < K; t++) {
        float xv = xr[z2s + 2 * t];
        float yv = yr[z2s + 2 * t];
        a0 += xv; a1 += yv; a2 += xv * xv; a3 += yv * yv; a4 += xv * yv;
    }
    out[0 * stride] = a0;
    out[1 * stride] = a1;
    out[2 * stride] = a2;
    out[3 * stride] = a3;
    out[4 * stride] = a4;
}

// ---------------------------------------------------------------------------
// sc1 body with parity-group factorization.
// Stage A: per (row, group) 5-element group sums of the 5 field products.
//   even groups g<16:  z2 = 10g + {0,2,4,6,8}
//   odd groups g>=16:  z2 = 10(g-16)+5 + {0,2,4,6,8}
// Stage B: window(o2) = sum of 4 consecutive groups of its parity:
//   o2=2m   -> even groups m..m+3
//   o2=2m+1 -> odd groups m..m+3
// gs layout: gs[rl*160 + f*32 + g]
// ---------------------------------------------------------------------------
__device__ __forceinline__ void body_sc1(int bid, const float* __restrict__ x,
                                         const float* __restrict__ y, float* sm) {
    const int O = O1, NZ = NZ1c;
    float* zwin = sm;                    // [NZ][5][O] = 20000
    float* raw  = sm + NZ * 5 * O;       // 5248 (16B-aligned offset)
    float* gs   = sm + GS1OFF;           // [16][5][32] = 2560

    int z0 = bid % DIM;
    int b  = bid / DIM;
    int w    = threadIdx.x >> 5;
    int lane = threadIdx.x & 31;
    const float* xbase = x + (size_t)(b * DIM + z0) * DIM * DIM;
    const float* ybase = y + (size_t)(b * DIM + z0) * DIM * DIM;

    float4 fx0, fx1, fy0, fy1;
    ldrow(xbase + (size_t)w * DIM, lane, fx0, fx1);
    ldrow(ybase + (size_t)w * DIM, lane, fy0, fy1);

    for (int ib = 0; ib < 10; ib++) {
        __syncthreads();                          // prev stage A done w/ raw
        strow(raw + w * RP,        lane, fx0, fx1);
        strow(raw + (16 + w) * RP, lane, fy0, fy1);
        if (ib < 9) {
            int z1 = (ib + 1) * 16 + w;
            ldrow(xbase + (size_t)z1 * DIM, lane, fx0, fx1);
            ldrow(ybase + (size_t)z1 * DIM, lane, fy0, fy1);
        }
        __syncthreads();                          // raw visible

        // Stage A: 496 items (row, group)
        if (threadIdx.x < 496) {
            int rl = threadIdx.x / 31;
            int g  = threadIdx.x % 31;
            int z2b = (g < 16) ? 10 * g : 10 * (g - 16) + 5;
            const float* xr = raw + rl * RP + z2b;
            const float* yr = raw + (16 + rl) * RP + z2b;
            float s0 = 0.f, s1 = 0.f, s2 = 0.f, s3 = 0.f, s4 = 0.f;
#pragma unroll
            for (int k = 0; k < 5; k++) {
                float xv = xr[2 * k];
                float yv = yr[2 * k];
                s0 += xv; s1 += yv; s2 += xv * xv; s3 += yv * yv; s4 += xv * yv;
            }
            float* gp = gs + rl * 160 + g;
            gp[0]   = s0;
            gp[32]  = s1;
            gp[64]  = s2;
            gp[96]  = s3;
            gp[128] = s4;
        }
        __syncthreads();                          // gs ready

        // Stage B: 400 items (row, o2): window = 4 group sums
        if (threadIdx.x < 16 * O) {
            int rl = threadIdx.x / O;
            int o2 = threadIdx.x % O;
            int m  = o2 >> 1;
            int gb = (o2 & 1) ? (16 + m) : m;
            const float* gp = gs + rl * 160 + gb;
            float a0 = gp[0]   + gp[1]   + gp[2]   + gp[3];
            float a1 = gp[32]  + gp[33]  + gp[34]  + gp[35];
            float a2 = gp[64]  + gp[65]  + gp[66]  + gp[67];
            float a3 = gp[96]  + gp[97]  + gp[98]  + gp[99];
            float a4 = gp[128] + gp[129] + gp[130] + gp[131];
            float* zw = zwin + (size_t)(ib * 16 + rl) * 125 + o2;
            zw[0 * O] = a0;
            zw[1 * O] = a1;
            zw[2 * O] = a2;
            zw[3 * O] = a3;
            zw[4 * O] = a4;
        }
    }
    __syncthreads();

    const int ITEMS = 5 * O * O;
    for (int item = threadIdx.x; item < ITEMS; item += 512) {
        int f   = item / (O * O);
        int rem = item % (O * O);
        int o1  = rem / O;
        int o2  = rem % O;
        float acc = 0.f;
#pragma unroll
        for (int t = 0; t < 20; t++)
            acc += zwin[(size_t)(5 * o1 + 2 * t) * 125 + f * O + o2];
        g_bufB[OFF1 + f * FS1 + (((b * NZ) + z0) * O + o1) * O + o2] = acc;
    }
}

// ---------------------------------------------------------------------------
// sc02 body (champion R9): even planes (z = 2*zi), CH0=36, 2 chunks.
// ---------------------------------------------------------------------------
__device__ __forceinline__ void body_sc02(int bid, const float* __restrict__ x,
                                          const float* __restrict__ y, float* sm) {
    const int NZ = 80;
    float* zwin0 = sm;                          // [80][5][CH0] = 14400
    float* zwin2 = sm + NZ * 5 * CH0;           // [80][5][9]   = 3600
    float* raw   = zwin2 + NZ * 5 * O2;         // 18000 floats (16B aligned)

    int ch  = bid & 1;  bid >>= 1;
    int z0i = bid % NZ;
    int b   = bid / NZ;
    int z0  = 2 * z0i;
    int obase = ch * CH0;
    int w    = threadIdx.x >> 5;
    int lane = threadIdx.x & 31;
    const float* xbase = x + (size_t)(b * DIM + z0) * DIM * DIM;
    const float* ybase = y + (size_t)(b * DIM + z0) * DIM * DIM;

    float4 fx0, fx1, fy0, fy1;
    ldrow(xbase + (size_t)(2 * w) * DIM, lane, fx0, fx1);
    ldrow(ybase + (size_t)(2 * w) * DIM, lane, fy0, fy1);

    for (int ib = 0; ib < 5; ib++) {
        int rb = ib * 16;
        __syncthreads();
        strow(raw + w * RP,        lane, fx0, fx1);
        strow(raw + (16 + w) * RP, lane, fy0, fy1);
        if (ib < 4) {
            int z1 = 2 * (rb + 16 + w);
            ldrow(xbase + (size_t)z1 * DIM, lane, fx0, fx1);
            ldrow(ybase + (size_t)z1 * DIM, lane, fy0, fy1);
        }
        __syncthreads();

        int nit = (ch == 0) ? (16 * CH0 + 16 * O2) : (16 * CH0);
        for (int it = threadIdx.x; it < nit; it += 512) {
            if (it < 16 * CH0) {
                int rl  = it / CH0;
                int o2l = it % CH0;
                int o2  = obase + o2l;
                if (o2 < O0)
                    win5<10>(raw + rl * RP, raw + (16 + rl) * RP, 2 * o2,
                             zwin0 + (size_t)(rb + rl) * 5 * CH0 + o2l, CH0);
            } else {
                int it2 = it - 16 * CH0;
                int rl = it2 / O2;
                int o2 = it2 % O2;
                win5<40>(raw + rl * RP, raw + (16 + rl) * RP, 10 * o2,
                         zwin2 + (size_t)(rb + rl) * 5 * O2 + o2, O2);
            }
        }
    }
    __syncthreads();

    {
        const int ITEMS = 5 * O0 * CH0;
        for (int item = threadIdx.x; item < ITEMS; item += 512) {
            int f   = item / (O0 * CH0);
            int rem = item % (O0 * CH0);
            int o1  = rem / CH0;
            int o2l = rem % CH0;
            int o2  = obase + o2l;
            if (o2 >= O0) continue;
            float acc = 0.f;
#pragma unroll
            for (int t = 0; t < 10; t++)
                acc += zwin0[(size_t)(o1 + t) * 5 * CH0 + f * CH0 + o2l];
            g_bufB[OFF0 + f * FS0 + (((b * NZ) + z0i) * O0 + o1) * O0 + o2] = acc;
        }
    }
    if (ch == 0) {
        const int ITEMS = 5 * O2 * O2;
        for (int item = threadIdx.x; item < ITEMS; item += 512) {
            int f   = item / (O2 * O2);
            int rem = item % (O2 * O2);
            int o1  = rem / O2;
            int o2  = rem % O2;
            float acc = 0.f;
#pragma unroll
            for (int t = 0; t < 40; t++)
                acc += zwin2[(size_t)(5 * o1 + t) * 5 * O2 + f * O2 + o2];
            g_bufB[OFF2 + f * FS2 + (((b * NZ) + z0i) * O2 + o1) * O2 + o2] = acc;
        }
    }
}

__global__ __launch_bounds__(512) void fused_all(const float* __restrict__ x,
                                                 const float* __restrict__ y) {
    extern __shared__ float sm[];
    int b = blockIdx.x;
    if (b < G1) body_sc1(b, x, y, sm);
    else        body_sc02(b - G1, x, y, sm);
}

// ---------------------------------------------------------------------------
// pass34 (champion) + fused finalize
// ---------------------------------------------------------------------------
__device__ __forceinline__ float lncc_eval(float s0, float s1, float s2,
                                           float s3, float s4, float numel) {
    float xm = s0 / numel;
    float ym = s1 / numel;
    float cross = s4 - ym * s0 - xm * s1 + ym * xm * numel;
    float xvar  = s2 - 2.f * xm * s0 + xm * xm * numel;
    float yvar  = s3 - 2.f * ym * s1 + ym * ym * numel;
    return cross * cross / (xvar * yvar + 1e-5f);
}

template<int K, int O, int NZ, int B0, int TS, int OFF, int FS, int N3>
__device__ __forceinline__ float pass34_gather(int blk) {
    const float numel = (float)K * (float)K * (float)K;
    int idx = blk * 256 + threadIdx.x;
    if (idx >= N3) return 0.f;
    int o2 = idx % O;
    int r  = idx / O;
    int o1 = r % O;  r /= O;
    int o0 = r % O;
    int b  = r / O;
    int inbase = ((b * NZ + B0 * o0) * O + o1) * O + o2;
    const int tapstride = TS * O * O;
    float acc[5];
#pragma unroll
    for (int f = 0; f < 5; f++) {
        const float* p = g_bufB + OFF + f * FS + inbase;
        float a = 0.f;
#pragma unroll
        for (int t = 0; t < K; t++) a += p[t * tapstride];
        acc[f] = a;
    }
    return lncc_eval(acc[0], acc[1], acc[2], acc[3], acc[4], numel);
}

__device__ __forceinline__ float pass34_strip0(int blk) {
    int idx = blk * 256 + threadIdx.x;
    if (idx >= NT0S) return 0.f;
    int o2 = idx % O0;
    int r  = idx / O0;
    int o1 = r % O0;  r /= O0;
    int strip = r % NSTRIP0;
    int b     = r / NSTRIP0;
    int o0s = strip * STRIP0;
    int o0e = (o0s + STRIP0 < O0) ? o0s + STRIP0 : O0;
    const int PS = O0 * O0;
    int base = ((b * NZ0) * O0 + o1) * O0 + o2;
    const float* p0 = g_bufB + OFF0 + base;
    float a0 = 0.f, a1 = 0.f, a2 = 0.f, a3 = 0.f, a4 = 0.f;
    float vsum = 0.f;
    for (int z = o0s; z < o0e + 9; z++) {
        int off = z * PS;
        a0 += p0[off];
        a1 += p0[off + 1 * FS0];
        a2 += p0[off + 2 * FS0];
        a3 += p0[off + 3 * FS0];
        a4 += p0[off + 4 * FS0];
        if (z >= o0s + 9) {
            vsum += lncc_eval(a0, a1, a2, a3, a4, 1000.0f);
            int offt = (z - 9) * PS;
            a0 -= p0[offt];
            a1 -= p0[offt + 1 * FS0];
            a2 -= p0[offt + 2 * FS0];
            a3 -= p0[offt + 3 * FS0];
            a4 -= p0[offt + 4 * FS0];
        }
    }
    return vsum;
}

__global__ __launch_bounds__(256) void pass34_all(float* __restrict__ out) {
    int bb = blockIdx.x;
    float v;
    int pslot;
    if (bb < NBLK0S) {
        v = pass34_strip0(bb);
        pslot = PB0 + bb;
    } else if (bb < NBLK0S + NBLK1) {
        v = pass34_gather<20, O1, NZ1c, 5, 2, OFF1, FS1, N3_1>(bb - NBLK0S);
        pslot = PB1 + (bb - NBLK0S);
    } else {
        v = pass34_gather<40, O2, NZ2, 5, 1, OFF2, FS2, N3_2>(bb - NBLK0S - NBLK1);
        pslot = PB2 + (bb - NBLK0S - NBLK1);
    }

    __shared__ float wsum[8];
    int lane = threadIdx.x & 31;
    int wid  = threadIdx.x >> 5;
#pragma unroll
    for (int o = 16; o > 0; o >>= 1) v += __shfl_down_sync(0xffffffffu, v, o);
    if (lane == 0) wsum[wid] = v;
    __syncthreads();
    if (wid == 0) {
        v = (lane < 8) ? wsum[lane] : 0.f;
#pragma unroll
        for (int o = 4; o > 0; o >>= 1) v += __shfl_down_sync(0xffffffffu, v, o);
        if (lane == 0) g_partials[pslot] = v;
    }

    __shared__ bool isLast;
    __threadfence();
    if (threadIdx.x == 0) {
        unsigned int old = atomicAdd(&g_count, 1u);
        isLast = (old == TOTBLK - 1);
    }
    __syncthreads();
    if (!isLast) return;
    __threadfence();

    __shared__ float sh[256];
    const int   pbase[3] = {PB0, PB1, PB2};
    const int   nblk[3]  = {NBLK0S, NBLK1, NBLK2};
    const float ninv[3]  = {1.0f / N3_0, 1.0f / N3_1, 1.0f / N3_2};
    const float wsc[3]   = {0.1f, 0.3f, 0.6f};
    float total = 0.f;
    for (int sc = 0; sc < 3; sc++) {
        float a = 0.f;
        for (int i = threadIdx.x; i < nblk[sc]; i += 256) a += g_partials[pbase[sc] + i];
        sh[threadIdx.x] = a;
        __syncthreads();
#pragma unroll
        for (int st = 128; st > 0; st >>= 1) {
            if (threadIdx.x < st) sh[threadIdx.x] += sh[threadIdx.x + st];
            __syncthreads();
        }
        if (threadIdx.x == 0) total += (1.0f - sh[0] * ninv[sc]) * wsc[sc];
        __syncthreads();
    }
    if (threadIdx.x == 0) {
        out[0] = total;
        g_count = 0;
    }
}

extern "C" void kernel_launch(void* const* d_in, const int* in_sizes, int n_in,
                              void* d_out, int out_size) {
    const float* x = (const float*)d_in[0];
    const float* y = (const float*)d_in[1];
    float* out = (float*)d_out;

    cudaFuncSetAttribute(fused_all,
                         cudaFuncAttributeMaxDynamicSharedMemorySize, SMEM_ALL);

    fused_all<<<GALL, 512, SMEM_ALL>>>(x, y);
    pass34_all<<<TOTBLK, 256>>>(out);
}